// round 1
// baseline (speedup 1.0000x reference)
#include <cuda_runtime.h>
#include <cuda_bf16.h>
#include <math.h>

#define BATCH 128
#define SEQ   49
#define HID   512
#define VOCAB 32000
#define NSTEP 15
#define BH    (BATCH*HID)

// ---------------- device scratch (no allocation allowed) ----------------
__device__ float g_x[BATCH*NSTEP*HID];     // embedded+fc1 tokens
__device__ float g_keys[BATCH*SEQ*HID];    // W_k(features)
__device__ float g_q[BH];
__device__ float g_context[BH];            // attention context (K dim)
__device__ float g_ctx[BH];                // fc0(context)
__device__ float g_h[2*4*BH];              // ping-pong hidden states, 4 layers
__device__ float g_hs[NSTEP*BH];           // top-layer h per step (fc2 input)
__device__ float g_part[6*3*BH];           // K-split partial sums [chunk][gate][b*H+c]

// ---------------- init: zero h buffer 0 ----------------
__global__ void init_kernel() {
    int idx = blockIdx.x * 256 + threadIdx.x;
    if (idx < 4*BH) g_h[idx] = 0.f;
}

// ---------------- big GEMM: C = A @ W^T + bias ----------------
// BM=BN=128, BK=8, 256 threads, 8x8 per thread.
// AMODE 0: A row-major MxK.  AMODE 1: A row = emb[captions[...]] (gather).
// CMODE 0: C[m*ldN + n].     CMODE 1: fc2 scatter  m=t*128+b -> out[b][t][n].
template<int AMODE, int CMODE>
__global__ void gemm_big(const float* __restrict__ A, const float* __restrict__ W,
                         const float* __restrict__ bias, float* __restrict__ C,
                         int ldN, int Kd, const int* __restrict__ caps)
{
    __shared__ float As[8][132];
    __shared__ float Bs[8][132];
    const int tid = threadIdx.x;
    const int bm = blockIdx.y * 128;
    const int bn = blockIdx.x * 128;
    const int tx = tid & 15;          // col group
    const int ty = tid >> 4;          // row group
    const int arow = tid >> 1;        // 0..127 (tile row for loads)
    const int acol = (tid & 1) * 4;   // 0 or 4 (k offset)

    const float* a_row_ptr;
    if (AMODE == 1) {
        int m  = bm + arow;
        int bb = m / NSTEP;
        int tt = m - bb * NSTEP;
        a_row_ptr = A + (size_t)caps[bb * 16 + tt] * Kd;
    } else {
        a_row_ptr = A + (size_t)(bm + arow) * Kd;
    }
    const float* w_row_ptr = W + (size_t)(bn + arow) * Kd;

    float acc[8][8];
    #pragma unroll
    for (int i = 0; i < 8; i++)
        #pragma unroll
        for (int j = 0; j < 8; j++) acc[i][j] = 0.f;

    for (int k0 = 0; k0 < Kd; k0 += 8) {
        float4 av = *(const float4*)(a_row_ptr + k0 + acol);
        float4 wv = *(const float4*)(w_row_ptr + k0 + acol);
        As[acol+0][arow] = av.x; As[acol+1][arow] = av.y;
        As[acol+2][arow] = av.z; As[acol+3][arow] = av.w;
        Bs[acol+0][arow] = wv.x; Bs[acol+1][arow] = wv.y;
        Bs[acol+2][arow] = wv.z; Bs[acol+3][arow] = wv.w;
        __syncthreads();
        #pragma unroll
        for (int k = 0; k < 8; k++) {
            float af[8], bf[8];
            *(float4*)&af[0] = *(const float4*)&As[k][ty*8];
            *(float4*)&af[4] = *(const float4*)&As[k][ty*8+4];
            *(float4*)&bf[0] = *(const float4*)&Bs[k][tx*8];
            *(float4*)&bf[4] = *(const float4*)&Bs[k][tx*8+4];
            #pragma unroll
            for (int i = 0; i < 8; i++)
                #pragma unroll
                for (int j = 0; j < 8; j++)
                    acc[i][j] += af[i] * bf[j];
        }
        __syncthreads();
    }

    float bb_[8];
    #pragma unroll
    for (int j = 0; j < 8; j++) bb_[j] = bias[bn + tx*8 + j];

    #pragma unroll
    for (int i = 0; i < 8; i++) {
        int m = bm + ty*8 + i;
        float* cptr;
        if (CMODE == 0) {
            cptr = C + (size_t)m * ldN + bn + tx*8;
        } else {
            int tt = m >> 7, b = m & 127;
            cptr = C + ((size_t)b * NSTEP + tt) * VOCAB + bn + tx*8;
        }
        #pragma unroll
        for (int j = 0; j < 8; j += 4) {
            float4 v;
            v.x = acc[i][j+0] + bb_[j+0];
            v.y = acc[i][j+1] + bb_[j+1];
            v.z = acc[i][j+2] + bb_[j+2];
            v.w = acc[i][j+3] + bb_[j+3];
            *(float4*)(cptr + j) = v;
        }
    }
}

// ---------------- small GEMM: C(128x512) = A(128x512) @ W(512x512)^T + bias ----
// grid (8,4): BN=64, BM=32.  128 threads, 4x4 per thread.
__global__ void small_gemm(const float* __restrict__ A, const float* __restrict__ W,
                           const float* __restrict__ bias, float* __restrict__ C)
{
    __shared__ float xs[16][36];
    __shared__ float ws[16][68];
    const int tid = threadIdx.x;
    const int tx = tid & 15, ty = tid >> 4;   // tx: n quad, ty: m quad
    const int bm = blockIdx.y * 32, bn = blockIdx.x * 64;

    float acc[4][4];
    #pragma unroll
    for (int i = 0; i < 4; i++)
        #pragma unroll
        for (int j = 0; j < 4; j++) acc[i][j] = 0.f;

    for (int k0 = 0; k0 < 512; k0 += 16) {
        #pragma unroll
        for (int i = 0; i < 4; i++) {
            int idx = tid + i * 128;
            int kk = idx & 15, m = idx >> 4;
            xs[kk][m] = A[(size_t)(bm + m) * 512 + k0 + kk];
        }
        #pragma unroll
        for (int i = 0; i < 8; i++) {
            int idx = tid + i * 128;
            int kk = idx & 15, n = idx >> 4;
            ws[kk][n] = W[(size_t)(bn + n) * 512 + k0 + kk];
        }
        __syncthreads();
        #pragma unroll
        for (int k = 0; k < 16; k++) {
            float4 xv = *(const float4*)&xs[k][ty*4];
            float4 wv = *(const float4*)&ws[k][tx*4];
            float xa[4] = {xv.x, xv.y, xv.z, xv.w};
            float wa[4] = {wv.x, wv.y, wv.z, wv.w};
            #pragma unroll
            for (int i = 0; i < 4; i++)
                #pragma unroll
                for (int j = 0; j < 4; j++)
                    acc[i][j] += xa[i] * wa[j];
        }
        __syncthreads();
    }

    #pragma unroll
    for (int i = 0; i < 4; i++) {
        int m = bm + ty*4 + i;
        #pragma unroll
        for (int j = 0; j < 4; j++) {
            int n = bn + tx*4 + j;
            C[(size_t)m * 512 + n] = acc[i][j] + bias[n];
        }
    }
}

// ---------------- attention: one block per batch element ----------------
__global__ void attention_kernel(const float* __restrict__ q, const float* __restrict__ keys,
                                 const float* __restrict__ features, const float* __restrict__ v_w,
                                 const float* __restrict__ v_b, float* __restrict__ ctx)
{
    const int b = blockIdx.x;
    const int tid = threadIdx.x;   // 256
    __shared__ float qs[512];
    __shared__ float vw[512];
    __shared__ float e[64];

    qs[tid]       = q[b*512 + tid];
    qs[tid + 256] = q[b*512 + tid + 256];
    vw[tid]       = v_w[tid];
    vw[tid + 256] = v_w[tid + 256];
    __syncthreads();

    const int warp = tid >> 5, lane = tid & 31;
    for (int s = warp; s < SEQ; s += 8) {
        const float* kp = keys + ((size_t)b * SEQ + s) * 512;
        float acc = 0.f;
        #pragma unroll
        for (int k = lane; k < 512; k += 32)
            acc += tanhf(qs[k] + kp[k]) * vw[k];
        #pragma unroll
        for (int o = 16; o; o >>= 1) acc += __shfl_xor_sync(0xffffffffu, acc, o);
        if (!lane) e[s] = acc + v_b[0];
    }
    __syncthreads();

    if (warp == 0) {
        float v1 = (lane < SEQ) ? e[lane] : -1e30f;
        float v2 = (lane + 32 < SEQ) ? e[lane + 32] : -1e30f;
        float m = fmaxf(v1, v2);
        #pragma unroll
        for (int o = 16; o; o >>= 1) m = fmaxf(m, __shfl_xor_sync(0xffffffffu, m, o));
        float e1 = (lane < SEQ) ? expf(v1 - m) : 0.f;
        float e2 = (lane + 32 < SEQ) ? expf(v2 - m) : 0.f;
        float s = e1 + e2;
        #pragma unroll
        for (int o = 16; o; o >>= 1) s += __shfl_xor_sync(0xffffffffu, s, o);
        float inv = 1.f / s;
        if (lane < SEQ) e[lane] = e1 * inv;
        if (lane + 32 < SEQ) e[lane + 32] = e2 * inv;
    }
    __syncthreads();

    #pragma unroll
    for (int k = tid; k < 512; k += 256) {
        float acc = 0.f;
        const float* f = features + (size_t)b * SEQ * 512 + k;
        #pragma unroll 7
        for (int s = 0; s < SEQ; s++) acc += e[s] * f[(size_t)s * 512];
        ctx[b*512 + k] = acc;
    }
}

// ---------------- GRU fused GEMM (K-split, writes partials) ----------------
// grid (8 n-tiles of 64, 4 m-tiles of 32, nchunks of K=256), 128 threads, 4x4/thread.
// Gates r,z share wih/whh accumulation; gate n kept split input/hidden side.
__global__ void gru_gemm(const float* __restrict__ inA, int ldA,
                         const float* __restrict__ inB,
                         const float* __restrict__ h_old,
                         const float* __restrict__ wih,
                         const float* __restrict__ whh, int Kin)
{
    __shared__ float xs[16][36];
    __shared__ float ws[3][16][68];
    const int tid = threadIdx.x;
    const int tx = tid & 15, ty = tid >> 4;
    const int bm = blockIdx.y * 32, bn = blockIdx.x * 64;
    const int K0 = blockIdx.z * 256;
    const bool isH = (K0 >= Kin);

    const float* src; int sld; int koff;
    if (isH)            { src = h_old; sld = 512; koff = K0 - Kin; }
    else if (K0 < 512)  { src = inA;   sld = ldA; koff = K0; }
    else                { src = inB;   sld = 512; koff = K0 - 512; }
    const float* wsrc; int wld; int wkoff;
    if (isH) { wsrc = whh; wld = 512; wkoff = K0 - Kin; }
    else     { wsrc = wih; wld = Kin; wkoff = K0; }

    float aR[4][4], aZ[4][4], aN[4][4];
    #pragma unroll
    for (int i = 0; i < 4; i++)
        #pragma unroll
        for (int j = 0; j < 4; j++) { aR[i][j]=0.f; aZ[i][j]=0.f; aN[i][j]=0.f; }

    for (int kb = 0; kb < 256; kb += 16) {
        #pragma unroll
        for (int i = 0; i < 4; i++) {
            int idx = tid + i * 128;
            int kk = idx & 15, m = idx >> 4;
            xs[kk][m] = src[(size_t)(bm + m) * sld + koff + kb + kk];
        }
        #pragma unroll
        for (int i = 0; i < 24; i++) {
            int idx = tid + i * 128;
            int kk = idx & 15;
            int r  = idx >> 4;
            int n  = r & 63;
            int g  = r >> 6;
            ws[g][kk][n] = wsrc[(size_t)(g*512 + bn + n) * wld + wkoff + kb + kk];
        }
        __syncthreads();
        #pragma unroll
        for (int k = 0; k < 16; k++) {
            float4 xv = *(const float4*)&xs[k][ty*4];
            float4 wr = *(const float4*)&ws[0][k][tx*4];
            float4 wz = *(const float4*)&ws[1][k][tx*4];
            float4 wn = *(const float4*)&ws[2][k][tx*4];
            float xa[4] = {xv.x, xv.y, xv.z, xv.w};
            float ra[4] = {wr.x, wr.y, wr.z, wr.w};
            float za[4] = {wz.x, wz.y, wz.z, wz.w};
            float na[4] = {wn.x, wn.y, wn.z, wn.w};
            #pragma unroll
            for (int i = 0; i < 4; i++)
                #pragma unroll
                for (int j = 0; j < 4; j++) {
                    aR[i][j] += xa[i] * ra[j];
                    aZ[i][j] += xa[i] * za[j];
                    aN[i][j] += xa[i] * na[j];
                }
        }
        __syncthreads();
    }

    // write partials: g_part[(z*3+g)*BH + b*512 + c]
    const int z = blockIdx.z;
    float* pR = g_part + (size_t)(z*3 + 0) * BH;
    float* pZ = g_part + (size_t)(z*3 + 1) * BH;
    float* pN = g_part + (size_t)(z*3 + 2) * BH;
    #pragma unroll
    for (int i = 0; i < 4; i++) {
        int off = (bm + ty*4 + i) * 512 + bn + tx*4;
        *(float4*)(pR + off) = *(float4*)&aR[i][0];
        *(float4*)(pZ + off) = *(float4*)&aZ[i][0];
        *(float4*)(pN + off) = *(float4*)&aN[i][0];
    }
}

// ---------------- gate kernel: reduce K-split partials, apply GRU gates --------
__global__ void gate_kernel(int nchunks, int zin,
                            const float* __restrict__ bih, const float* __restrict__ bhh,
                            const float* __restrict__ h_old, float* __restrict__ h_new,
                            float* __restrict__ hs_out)
{
    int idx = blockIdx.x * 256 + threadIdx.x;   // < BH
    int c = idx & 511;
    float r = 0.f, z = 0.f, in = 0.f, hn = 0.f;
    for (int ch = 0; ch < zin; ch++) {
        r  += g_part[(size_t)(ch*3 + 0) * BH + idx];
        z  += g_part[(size_t)(ch*3 + 1) * BH + idx];
        in += g_part[(size_t)(ch*3 + 2) * BH + idx];
    }
    for (int ch = zin; ch < nchunks; ch++) {
        r  += g_part[(size_t)(ch*3 + 0) * BH + idx];
        z  += g_part[(size_t)(ch*3 + 1) * BH + idx];
        hn += g_part[(size_t)(ch*3 + 2) * BH + idx];
    }
    r  += bih[c]        + bhh[c];
    z  += bih[512 + c]  + bhh[512 + c];
    in += bih[1024 + c];
    hn += bhh[1024 + c];
    r = 1.f / (1.f + expf(-r));
    z = 1.f / (1.f + expf(-z));
    float n = tanhf(in + r * hn);
    float h = (1.f - z) * n + z * h_old[idx];
    h_new[idx] = h;
    if (hs_out) hs_out[idx] = h;
}

// ---------------- host launch ----------------
extern "C" void kernel_launch(void* const* d_in, const int* in_sizes, int n_in,
                              void* d_out, int out_size)
{
    const float* features = (const float*)d_in[0];
    const int*   caps     = (const int*)  d_in[1];
    const float* emb      = (const float*)d_in[2];
    const float* fc1_w    = (const float*)d_in[3];
    const float* fc1_b    = (const float*)d_in[4];
    const float* fc0_w    = (const float*)d_in[5];
    const float* fc0_b    = (const float*)d_in[6];
    const float* wq       = (const float*)d_in[7];
    const float* bq       = (const float*)d_in[8];
    const float* wk       = (const float*)d_in[9];
    const float* bk       = (const float*)d_in[10];
    const float* v_w      = (const float*)d_in[11];
    const float* v_b      = (const float*)d_in[12];
    const float* wih0     = (const float*)d_in[13];
    const float* whh0     = (const float*)d_in[14];
    const float* bih0     = (const float*)d_in[15];
    const float* bhh0     = (const float*)d_in[16];
    const float* wihr     = (const float*)d_in[17];
    const float* whhr     = (const float*)d_in[18];
    const float* bihr     = (const float*)d_in[19];
    const float* bhhr     = (const float*)d_in[20];
    const float* fc2_w    = (const float*)d_in[21];
    const float* fc2_b    = (const float*)d_in[22];
    float* out = (float*)d_out;

    float *px, *pkeys, *pq, *pcontext, *pctx, *ph, *phs;
    cudaGetSymbolAddress((void**)&px,       g_x);
    cudaGetSymbolAddress((void**)&pkeys,    g_keys);
    cudaGetSymbolAddress((void**)&pq,       g_q);
    cudaGetSymbolAddress((void**)&pcontext, g_context);
    cudaGetSymbolAddress((void**)&pctx,     g_ctx);
    cudaGetSymbolAddress((void**)&ph,       g_h);
    cudaGetSymbolAddress((void**)&phs,      g_hs);

    init_kernel<<<1024, 256>>>();

    // x = emb[captions[:, :15]] @ fc1_w^T + fc1_b   (M=1920)
    gemm_big<1,0><<<dim3(4, 15), 256>>>(emb, fc1_w, fc1_b, px, 512, 512, caps);
    // keys = features @ wk^T + bk                   (M=6272)
    gemm_big<0,0><<<dim3(4, 49), 256>>>(features, wk, bk, pkeys, 512, 512, nullptr);

    for (int t = 0; t < NSTEP; t++) {
        const float* hold = ph + (t & 1) * (4 * BH);
        float*       hnew = ph + ((t & 1) ^ 1) * (4 * BH);

        // q = h[3] @ wq^T + bq
        small_gemm<<<dim3(8, 4), 128>>>(hold + 3 * BH, wq, bq, pq);
        attention_kernel<<<128, 256>>>(pq, pkeys, features, v_w, v_b, pcontext);
        // ctx = context @ fc0_w^T + fc0_b
        small_gemm<<<dim3(8, 4), 128>>>(pcontext, fc0_w, fc0_b, pctx);

        // layer 0: input = concat(x_t, ctx), Kin=1024, total K=1536 -> 6 chunks
        gru_gemm<<<dim3(8, 4, 6), 128>>>(px + t * HID, NSTEP * HID, pctx,
                                         hold, wih0, whh0, 1024);
        gate_kernel<<<256, 256>>>(6, 4, bih0, bhh0, hold, hnew, nullptr);

        for (int l = 1; l < 4; l++) {
            gru_gemm<<<dim3(8, 4, 4), 128>>>(hnew + (l - 1) * BH, HID, nullptr,
                                             hold + l * BH,
                                             wihr + (size_t)(l - 1) * 1536 * 512,
                                             whhr + (size_t)(l - 1) * 1536 * 512, 512);
            gate_kernel<<<256, 256>>>(4, 2,
                                      bihr + (l - 1) * 1536, bhhr + (l - 1) * 1536,
                                      hold + l * BH, hnew + l * BH,
                                      (l == 3) ? (phs + t * BH) : nullptr);
        }
    }

    // out[b][t][:] = hs[t][b] @ fc2_w^T + fc2_b   (M=1920, N=32000)
    gemm_big<0,1><<<dim3(250, 15), 256>>>(phs, fc2_w, fc2_b, out, 32000, 512, nullptr);
}

// round 3
// speedup vs baseline: 1.2332x; 1.2332x over previous
#include <cuda_runtime.h>
#include <cuda_bf16.h>
#include <math.h>
#include <cstdint>

#define BATCH 128
#define SEQ   49
#define HID   512
#define VOCAB 32000
#define NSTEP 15
#define BH    (BATCH*HID)

// ---------------- device scratch ----------------
__device__ float g_x[BATCH*NSTEP*HID];
__device__ float g_keys[BATCH*SEQ*HID];
__device__ float g_ctx[BH];
__device__ float g_h[2*4*BH];
__device__ float g_hs[NSTEP*BH];            // tf32-rounded top-layer h
__device__ float g_part[6*3*BH];
__device__ float g_w2[VOCAB*HID];           // tf32-rounded fc2 weights

__device__ __forceinline__ float rtf32(float x) {
    uint32_t r; asm("cvt.rna.tf32.f32 %0, %1;" : "=r"(r) : "f"(x));
    return __uint_as_float(r);
}

// ---------------- init ----------------
__global__ void init_kernel() {
    int idx = blockIdx.x * 256 + threadIdx.x;
    if (idx < 4*BH) g_h[idx] = 0.f;
}

// ---------------- tf32-round fc2 weights ----------------
__global__ void cvt_w2_kernel(const float* __restrict__ w) {
    int i = blockIdx.x * 256 + threadIdx.x;
    float4 v = ((const float4*)w)[i];
    float4 r;
    r.x = rtf32(v.x); r.y = rtf32(v.y); r.z = rtf32(v.z); r.w = rtf32(v.w);
    ((float4*)g_w2)[i] = r;
}

// ---------------- big SIMT GEMM (precompute only) ----------------
template<int AMODE>
__global__ void gemm_big(const float* __restrict__ A, const float* __restrict__ W,
                         const float* __restrict__ bias, float* __restrict__ C,
                         int ldN, int Kd, const int* __restrict__ caps)
{
    __shared__ float As[8][132];
    __shared__ float Bs[8][132];
    const int tid = threadIdx.x;
    const int bm = blockIdx.y * 128;
    const int bn = blockIdx.x * 128;
    const int tx = tid & 15, ty = tid >> 4;
    const int arow = tid >> 1;
    const int acol = (tid & 1) * 4;

    const float* a_row_ptr;
    if (AMODE == 1) {
        int m = bm + arow;
        int bb = m / NSTEP, tt = m - bb * NSTEP;
        a_row_ptr = A + (size_t)caps[bb * 16 + tt] * Kd;
    } else {
        a_row_ptr = A + (size_t)(bm + arow) * Kd;
    }
    const float* w_row_ptr = W + (size_t)(bn + arow) * Kd;

    float acc[8][8];
    #pragma unroll
    for (int i = 0; i < 8; i++)
        #pragma unroll
        for (int j = 0; j < 8; j++) acc[i][j] = 0.f;

    for (int k0 = 0; k0 < Kd; k0 += 8) {
        float4 av = *(const float4*)(a_row_ptr + k0 + acol);
        float4 wv = *(const float4*)(w_row_ptr + k0 + acol);
        As[acol+0][arow] = av.x; As[acol+1][arow] = av.y;
        As[acol+2][arow] = av.z; As[acol+3][arow] = av.w;
        Bs[acol+0][arow] = wv.x; Bs[acol+1][arow] = wv.y;
        Bs[acol+2][arow] = wv.z; Bs[acol+3][arow] = wv.w;
        __syncthreads();
        #pragma unroll
        for (int k = 0; k < 8; k++) {
            float af[8], bf[8];
            *(float4*)&af[0] = *(const float4*)&As[k][ty*8];
            *(float4*)&af[4] = *(const float4*)&As[k][ty*8+4];
            *(float4*)&bf[0] = *(const float4*)&Bs[k][tx*8];
            *(float4*)&bf[4] = *(const float4*)&Bs[k][tx*8+4];
            #pragma unroll
            for (int i = 0; i < 8; i++)
                #pragma unroll
                for (int j = 0; j < 8; j++)
                    acc[i][j] += af[i] * bf[j];
        }
        __syncthreads();
    }
    #pragma unroll
    for (int i = 0; i < 8; i++) {
        int m = bm + ty*8 + i;
        float* cptr = C + (size_t)m * ldN + bn + tx*8;
        #pragma unroll
        for (int j = 0; j < 8; j += 4) {
            float4 v;
            v.x = acc[i][j+0] + bias[bn + tx*8 + j+0];
            v.y = acc[i][j+1] + bias[bn + tx*8 + j+1];
            v.z = acc[i][j+2] + bias[bn + tx*8 + j+2];
            v.w = acc[i][j+3] + bias[bn + tx*8 + j+3];
            *(float4*)(cptr + j) = v;
        }
    }
}

// ---------------- fused attention: q=h3@wq^T, tanh-attn, ctx=context@fc0^T ----
__global__ void att_fused(const float* __restrict__ h3, const float* __restrict__ wq,
                          const float* __restrict__ bq, const float* __restrict__ keys,
                          const float* __restrict__ features, const float* __restrict__ v_w,
                          const float* __restrict__ v_b, const float* __restrict__ fc0_w,
                          const float* __restrict__ fc0_b, float* __restrict__ ctx_out)
{
    const int b = blockIdx.x;
    const int tid = threadIdx.x;   // 256
    __shared__ float hs_[512], qs[512], vw[512], cs[512];
    __shared__ float e[64];

    for (int i = tid; i < 512; i += 256) { hs_[i] = h3[b*512 + i]; vw[i] = v_w[i]; }
    __syncthreads();

    for (int j = tid; j < 512; j += 256) {
        const float* wr = wq + (size_t)j * 512;
        float acc = 0.f;
        #pragma unroll 8
        for (int k = 0; k < 512; k += 4) {
            float4 w = *(const float4*)(wr + k);
            acc += hs_[k]*w.x + hs_[k+1]*w.y + hs_[k+2]*w.z + hs_[k+3]*w.w;
        }
        qs[j] = acc + bq[j];
    }
    __syncthreads();

    const int warp = tid >> 5, lane = tid & 31;
    for (int s = warp; s < SEQ; s += 8) {
        const float* kp = keys + ((size_t)b * SEQ + s) * 512;
        float acc = 0.f;
        #pragma unroll
        for (int k = lane; k < 512; k += 32)
            acc += tanhf(qs[k] + kp[k]) * vw[k];
        #pragma unroll
        for (int o = 16; o; o >>= 1) acc += __shfl_xor_sync(0xffffffffu, acc, o);
        if (!lane) e[s] = acc + v_b[0];
    }
    __syncthreads();

    if (warp == 0) {
        float v1 = (lane < SEQ) ? e[lane] : -1e30f;
        float v2 = (lane + 32 < SEQ) ? e[lane + 32] : -1e30f;
        float m = fmaxf(v1, v2);
        #pragma unroll
        for (int o = 16; o; o >>= 1) m = fmaxf(m, __shfl_xor_sync(0xffffffffu, m, o));
        float e1 = (lane < SEQ) ? expf(v1 - m) : 0.f;
        float e2 = (lane + 32 < SEQ) ? expf(v2 - m) : 0.f;
        float s = e1 + e2;
        #pragma unroll
        for (int o = 16; o; o >>= 1) s += __shfl_xor_sync(0xffffffffu, s, o);
        float inv = 1.f / s;
        if (lane < SEQ) e[lane] = e1 * inv;
        if (lane + 32 < SEQ) e[lane + 32] = e2 * inv;
    }
    __syncthreads();

    for (int k = tid; k < 512; k += 256) {
        float acc = 0.f;
        const float* f = features + (size_t)b * SEQ * 512 + k;
        #pragma unroll 7
        for (int s = 0; s < SEQ; s++) acc += e[s] * f[(size_t)s * 512];
        cs[k] = acc;
    }
    __syncthreads();

    for (int j = tid; j < 512; j += 256) {
        const float* wr = fc0_w + (size_t)j * 512;
        float acc = 0.f;
        #pragma unroll 8
        for (int k = 0; k < 512; k += 4) {
            float4 w = *(const float4*)(wr + k);
            acc += cs[k]*w.x + cs[k+1]*w.y + cs[k+2]*w.z + cs[k+3]*w.w;
        }
        ctx_out[b*512 + j] = acc + fc0_b[j];
    }
}

// ---------------- GRU fused GEMM (K-split partials) ----------------
__global__ void gru_gemm(const float* __restrict__ inA, int ldA,
                         const float* __restrict__ inB,
                         const float* __restrict__ h_old,
                         const float* __restrict__ wih,
                         const float* __restrict__ whh, int Kin)
{
    __shared__ float xs[16][36];
    __shared__ float ws[3][16][68];
    const int tid = threadIdx.x;
    const int tx = tid & 15, ty = tid >> 4;
    const int bm = blockIdx.y * 32, bn = blockIdx.x * 64;
    const int K0 = blockIdx.z * 256;
    const bool isH = (K0 >= Kin);

    const float* src; int sld; int koff;
    if (isH)            { src = h_old; sld = 512; koff = K0 - Kin; }
    else if (K0 < 512)  { src = inA;   sld = ldA; koff = K0; }
    else                { src = inB;   sld = 512; koff = K0 - 512; }
    const float* wsrc; int wld; int wkoff;
    if (isH) { wsrc = whh; wld = 512; wkoff = K0 - Kin; }
    else     { wsrc = wih; wld = Kin; wkoff = K0; }

    float aR[4][4], aZ[4][4], aN[4][4];
    #pragma unroll
    for (int i = 0; i < 4; i++)
        #pragma unroll
        for (int j = 0; j < 4; j++) { aR[i][j]=0.f; aZ[i][j]=0.f; aN[i][j]=0.f; }

    for (int kb = 0; kb < 256; kb += 16) {
        #pragma unroll
        for (int i = 0; i < 4; i++) {
            int idx = tid + i * 128;
            int kk = idx & 15, m = idx >> 4;
            xs[kk][m] = src[(size_t)(bm + m) * sld + koff + kb + kk];
        }
        #pragma unroll
        for (int i = 0; i < 24; i++) {
            int idx = tid + i * 128;
            int kk = idx & 15;
            int r  = idx >> 4;
            int n  = r & 63;
            int g  = r >> 6;
            ws[g][kk][n] = wsrc[(size_t)(g*512 + bn + n) * wld + wkoff + kb + kk];
        }
        __syncthreads();
        #pragma unroll
        for (int k = 0; k < 16; k++) {
            float4 xv = *(const float4*)&xs[k][ty*4];
            float4 wr = *(const float4*)&ws[0][k][tx*4];
            float4 wz = *(const float4*)&ws[1][k][tx*4];
            float4 wn = *(const float4*)&ws[2][k][tx*4];
            float xa[4] = {xv.x, xv.y, xv.z, xv.w};
            float ra[4] = {wr.x, wr.y, wr.z, wr.w};
            float za[4] = {wz.x, wz.y, wz.z, wz.w};
            float na[4] = {wn.x, wn.y, wn.z, wn.w};
            #pragma unroll
            for (int i = 0; i < 4; i++)
                #pragma unroll
                for (int j = 0; j < 4; j++) {
                    aR[i][j] += xa[i] * ra[j];
                    aZ[i][j] += xa[i] * za[j];
                    aN[i][j] += xa[i] * na[j];
                }
        }
        __syncthreads();
    }

    const int z = blockIdx.z;
    float* pR = g_part + (size_t)(z*3 + 0) * BH;
    float* pZ = g_part + (size_t)(z*3 + 1) * BH;
    float* pN = g_part + (size_t)(z*3 + 2) * BH;
    #pragma unroll
    for (int i = 0; i < 4; i++) {
        int off = (bm + ty*4 + i) * 512 + bn + tx*4;
        *(float4*)(pR + off) = *(float4*)&aR[i][0];
        *(float4*)(pZ + off) = *(float4*)&aZ[i][0];
        *(float4*)(pN + off) = *(float4*)&aN[i][0];
    }
}

// ---------------- gate kernel ----------------
__global__ void gate_kernel(int nchunks, int zin,
                            const float* __restrict__ bih, const float* __restrict__ bhh,
                            const float* __restrict__ h_old, float* __restrict__ h_new,
                            float* __restrict__ hs_out)
{
    int idx = blockIdx.x * 256 + threadIdx.x;
    int c = idx & 511;
    float r = 0.f, z = 0.f, in = 0.f, hn = 0.f;
    for (int ch = 0; ch < zin; ch++) {
        r  += g_part[(size_t)(ch*3 + 0) * BH + idx];
        z  += g_part[(size_t)(ch*3 + 1) * BH + idx];
        in += g_part[(size_t)(ch*3 + 2) * BH + idx];
    }
    for (int ch = zin; ch < nchunks; ch++) {
        r  += g_part[(size_t)(ch*3 + 0) * BH + idx];
        z  += g_part[(size_t)(ch*3 + 1) * BH + idx];
        hn += g_part[(size_t)(ch*3 + 2) * BH + idx];
    }
    r  += bih[c]        + bhh[c];
    z  += bih[512 + c]  + bhh[512 + c];
    in += bih[1024 + c];
    hn += bhh[1024 + c];
    r = 1.f / (1.f + expf(-r));
    z = 1.f / (1.f + expf(-z));
    float n = tanhf(in + r * hn);
    float h = (1.f - z) * n + z * h_old[idx];
    h_new[idx] = h;
    if (hs_out) hs_out[idx] = rtf32(h);
}

// ---------------- fc2 via mma.sync tf32 ----------------
// C[1920 x 32000] = hs @ w2^T + fc2_b, scattered to out[b][t][n].
// Block tile 128x256, BK=32, double-buffered smem; 8 warps, warp tile 64x64.
#define FC2_PAD   36
#define FC2_ASZ   (128*FC2_PAD)     // floats per A stage
#define FC2_BSZ   (256*FC2_PAD)
#define FC2_SMEM  ((2*FC2_ASZ + 2*FC2_BSZ)*4)

__device__ __forceinline__ void hmma_tf32(float& c0, float& c1, float& c2, float& c3,
                                          uint32_t a0, uint32_t a1, uint32_t a2, uint32_t a3,
                                          uint32_t b0, uint32_t b1) {
    asm volatile("mma.sync.aligned.m16n8k8.row.col.f32.tf32.tf32.f32 "
                 "{%0,%1,%2,%3}, {%4,%5,%6,%7}, {%8,%9}, {%0,%1,%2,%3};"
                 : "+f"(c0), "+f"(c1), "+f"(c2), "+f"(c3)
                 : "r"(a0), "r"(a1), "r"(a2), "r"(a3), "r"(b0), "r"(b1));
}

__global__ void __launch_bounds__(256, 1) fc2_mma(
    const float* __restrict__ A, const float* __restrict__ Bw,
    const float* __restrict__ bias, float* __restrict__ out)
{
    extern __shared__ float sm[];
    float* As = sm;                    // [2][128][36]
    float* Bs = sm + 2*FC2_ASZ;        // [2][256][36]

    const int tid  = threadIdx.x;
    const int lane = tid & 31, wid = tid >> 5;
    const int wm = (wid >> 2) * 64;    // warp M offset (0/64)
    const int wn = (wid & 3)  * 64;    // warp N offset
    const int grp = lane >> 2;         // 0..7
    const int tig = lane & 3;          // 0..3
    const int bn = blockIdx.x * 256;
    const int t  = blockIdx.y;

    const float* Ab = A  + (size_t)t  * 128 * 512;
    const float* Bb = Bw + (size_t)bn * 512;

    const int lrowA = tid >> 3;        // 0..31
    const int lc4   = (tid & 7) * 4;   // 0..28

    float acc[4][8][4];
    #pragma unroll
    for (int i = 0; i < 4; i++)
        #pragma unroll
        for (int j = 0; j < 8; j++)
            #pragma unroll
            for (int k = 0; k < 4; k++) acc[i][j][k] = 0.f;

    float4 ra[4], rb[8];
    // prologue: load kt=0
    #pragma unroll
    for (int p = 0; p < 4; p++)
        ra[p] = *(const float4*)(Ab + (size_t)(p*32 + lrowA) * 512 + lc4);
    #pragma unroll
    for (int p = 0; p < 8; p++)
        rb[p] = *(const float4*)(Bb + (size_t)(p*32 + lrowA) * 512 + lc4);
    #pragma unroll
    for (int p = 0; p < 4; p++)
        *(float4*)(As + (p*32 + lrowA)*FC2_PAD + lc4) = ra[p];
    #pragma unroll
    for (int p = 0; p < 8; p++)
        *(float4*)(Bs + (p*32 + lrowA)*FC2_PAD + lc4) = rb[p];
    __syncthreads();

    #pragma unroll 1
    for (int kt = 0; kt < 16; kt++) {
        const int buf = kt & 1;
        const float* Asb = As + buf * FC2_ASZ;
        const float* Bsb = Bs + buf * FC2_BSZ;

        if (kt < 15) {
            const float* Aq = Ab + (kt+1)*32;
            const float* Bq = Bb + (kt+1)*32;
            #pragma unroll
            for (int p = 0; p < 4; p++)
                ra[p] = *(const float4*)(Aq + (size_t)(p*32 + lrowA) * 512 + lc4);
            #pragma unroll
            for (int p = 0; p < 8; p++)
                rb[p] = *(const float4*)(Bq + (size_t)(p*32 + lrowA) * 512 + lc4);
        }

        #pragma unroll
        for (int k8 = 0; k8 < 4; k8++) {
            const int kc = k8*8 + tig;
            uint32_t af[4][4];
            #pragma unroll
            for (int mi = 0; mi < 4; mi++) {
                const float* ar = Asb + (wm + mi*16 + grp)*FC2_PAD;
                af[mi][0] = __float_as_uint(ar[kc]);
                af[mi][1] = __float_as_uint(ar[8*FC2_PAD + kc]);
                af[mi][2] = __float_as_uint(ar[kc + 4]);
                af[mi][3] = __float_as_uint(ar[8*FC2_PAD + kc + 4]);
            }
            #pragma unroll
            for (int nj = 0; nj < 8; nj++) {
                const float* br = Bsb + (wn + nj*8 + grp)*FC2_PAD + k8*8;
                uint32_t b0 = __float_as_uint(br[tig]);
                uint32_t b1 = __float_as_uint(br[tig + 4]);
                #pragma unroll
                for (int mi = 0; mi < 4; mi++)
                    hmma_tf32(acc[mi][nj][0], acc[mi][nj][1], acc[mi][nj][2], acc[mi][nj][3],
                              af[mi][0], af[mi][1], af[mi][2], af[mi][3], b0, b1);
            }
        }

        if (kt < 15) {
            float* Asn = As + (buf ^ 1) * FC2_ASZ;
            float* Bsn = Bs + (buf ^ 1) * FC2_BSZ;
            #pragma unroll
            for (int p = 0; p < 4; p++)
                *(float4*)(Asn + (p*32 + lrowA)*FC2_PAD + lc4) = ra[p];
            #pragma unroll
            for (int p = 0; p < 8; p++)
                *(float4*)(Bsn + (p*32 + lrowA)*FC2_PAD + lc4) = rb[p];
        }
        __syncthreads();
    }

    // epilogue: bias + scatter out[b][t][n]
    #pragma unroll
    for (int mi = 0; mi < 4; mi++) {
        const int b0 = wm + mi*16 + grp;
        float* o0 = out + ((size_t)b0       * NSTEP + t) * VOCAB + bn + wn;
        float* o8 = out + ((size_t)(b0 + 8) * NSTEP + t) * VOCAB + bn + wn;
        #pragma unroll
        for (int nj = 0; nj < 8; nj++) {
            const int n = nj*8 + 2*tig;
            float bx = bias[bn + wn + n];
            float by = bias[bn + wn + n + 1];
            float2 v0 = make_float2(acc[mi][nj][0] + bx, acc[mi][nj][1] + by);
            float2 v1 = make_float2(acc[mi][nj][2] + bx, acc[mi][nj][3] + by);
            *(float2*)(o0 + n) = v0;
            *(float2*)(o8 + n) = v1;
        }
    }
}

// ---------------- host launch ----------------
extern "C" void kernel_launch(void* const* d_in, const int* in_sizes, int n_in,
                              void* d_out, int out_size)
{
    const float* features = (const float*)d_in[0];
    const int*   caps     = (const int*)  d_in[1];
    const float* emb      = (const float*)d_in[2];
    const float* fc1_w    = (const float*)d_in[3];
    const float* fc1_b    = (const float*)d_in[4];
    const float* fc0_w    = (const float*)d_in[5];
    const float* fc0_b    = (const float*)d_in[6];
    const float* wq       = (const float*)d_in[7];
    const float* bq       = (const float*)d_in[8];
    const float* wk       = (const float*)d_in[9];
    const float* bk       = (const float*)d_in[10];
    const float* v_w      = (const float*)d_in[11];
    const float* v_b      = (const float*)d_in[12];
    const float* wih0     = (const float*)d_in[13];
    const float* whh0     = (const float*)d_in[14];
    const float* bih0     = (const float*)d_in[15];
    const float* bhh0     = (const float*)d_in[16];
    const float* wihr     = (const float*)d_in[17];
    const float* whhr     = (const float*)d_in[18];
    const float* bihr     = (const float*)d_in[19];
    const float* bhhr     = (const float*)d_in[20];
    const float* fc2_b    = (const float*)d_in[22];
    const float* fc2_w    = (const float*)d_in[21];
    float* out = (float*)d_out;

    float *px, *pkeys, *pctx, *ph, *phs, *pw2;
    cudaGetSymbolAddress((void**)&px,    g_x);
    cudaGetSymbolAddress((void**)&pkeys, g_keys);
    cudaGetSymbolAddress((void**)&pctx,  g_ctx);
    cudaGetSymbolAddress((void**)&ph,    g_h);
    cudaGetSymbolAddress((void**)&phs,   g_hs);
    cudaGetSymbolAddress((void**)&pw2,   g_w2);

    cudaFuncSetAttribute(fc2_mma, cudaFuncAttributeMaxDynamicSharedMemorySize, FC2_SMEM);

    init_kernel<<<1024, 256>>>();
    cvt_w2_kernel<<<VOCAB*HID/4/256, 256>>>(fc2_w);

    gemm_big<1><<<dim3(4, 15), 256>>>(emb, fc1_w, fc1_b, px, 512, 512, caps);
    gemm_big<0><<<dim3(4, 49), 256>>>(features, wk, bk, pkeys, 512, 512, nullptr);

    for (int t = 0; t < NSTEP; t++) {
        const float* hold = ph + (t & 1) * (4 * BH);
        float*       hnew = ph + ((t & 1) ^ 1) * (4 * BH);

        att_fused<<<128, 256>>>(hold + 3 * BH, wq, bq, pkeys, features,
                                v_w, v_b, fc0_w, fc0_b, pctx);

        gru_gemm<<<dim3(8, 4, 6), 128>>>(px + t * HID, NSTEP * HID, pctx,
                                         hold, wih0, whh0, 1024);
        gate_kernel<<<256, 256>>>(6, 4, bih0, bhh0, hold, hnew, nullptr);

        for (int l = 1; l < 4; l++) {
            gru_gemm<<<dim3(8, 4, 4), 128>>>(hnew + (l - 1) * BH, HID, nullptr,
                                             hold + l * BH,
                                             wihr + (size_t)(l - 1) * 1536 * 512,
                                             whhr + (size_t)(l - 1) * 1536 * 512, 512);
            gate_kernel<<<256, 256>>>(4, 2,
                                      bihr + (l - 1) * 1536, bhhr + (l - 1) * 1536,
                                      hold + l * BH, hnew + l * BH,
                                      (l == 3) ? (phs + t * BH) : nullptr);
        }
    }

    fc2_mma<<<dim3(VOCAB/256, NSTEP), 256, FC2_SMEM>>>(phs, pw2, fc2_b, out);
}